// round 2
// baseline (speedup 1.0000x reference)
#include <cuda_runtime.h>
#include <math.h>

#define N_TOK 65536
#define DD 64
#define KC 1024
#define NELEM 4194304
#define OFF_LOSS 4194304
#define OFF_IDX  4194305
#define OFF_EMB  4259841
#define OFF_CS   4325377
#define OFF_EMAW 4326401

// ---------------- scratch (device globals; no allocations allowed) ----------
__device__ float  g_xrot[N_TOK * DD];   // rotated tokens, row-major [n][d]
__device__ float  g_x2[N_TOK];          // ||x_rot||^2 per token (fp32, ref-like)
__device__ float  g_e2[KC];             // ||e||^2 per code
__device__ int    g_idx[N_TOK];
__device__ int    g_counts[KC];
__device__ double g_dw[KC * DD];        // segment-sum of x_rot (fp64 accum)
__device__ double g_mse;                // sum of (quant-x)^2
__device__ float  g_newcs[KC];

typedef unsigned long long ull;

__device__ __forceinline__ ull pk2(float lo, float hi) {
    ull r; asm("mov.b64 %0, {%1, %2};" : "=l"(r) : "f"(lo), "f"(hi)); return r;
}
__device__ __forceinline__ void upk2(ull v, float &lo, float &hi) {
    asm("mov.b64 {%0, %1}, %2;" : "=f"(lo), "=f"(hi) : "l"(v));
}
__device__ __forceinline__ ull fma2(ull a, ull b, ull c) {
    ull d; asm("fma.rn.f32x2 %0, %1, %2, %3;" : "=l"(d) : "l"(a), "l"(b), "l"(c)); return d;
}

// ---------------- kernel: zero scratch --------------------------------------
__global__ void k_zero() {
    int i = blockIdx.x * 256 + threadIdx.x;
    if (i < KC * DD) g_dw[i] = 0.0;
    if (i < KC) g_counts[i] = 0;
    if (i == 0) g_mse = 0.0;
}

// ---------------- kernel: rotation x_rot = x_flat @ R, plus x2 --------------
// block: 256 threads handles 64 tokens (one b, 64 consecutive hw), full D
__global__ void k_rotate(const float* __restrict__ X, const float* __restrict__ R) {
    __shared__ float Rs[64 * 64];
    __shared__ float xs[64 * 64];   // xs[c][w]
    __shared__ float sp[4][64];
    int t = threadIdx.x;
    int b = blockIdx.x >> 6;
    int hw0 = (blockIdx.x & 63) << 6;

    for (int i = t; i < 4096; i += 256) Rs[i] = R[i];
    for (int i = t; i < 4096; i += 256) {
        int c = i >> 6, w = i & 63;
        xs[i] = X[(((b << 6) + c) << 12) + hw0 + w];
    }
    __syncthreads();

    int tok = t & 63, jg = t >> 6;          // jg in 0..3 -> 16 output dims each
    float r[16];
#pragma unroll
    for (int i = 0; i < 16; i++) r[i] = 0.f;

#pragma unroll 8
    for (int c = 0; c < 64; c++) {
        float xv = xs[(c << 6) + tok];
        const float4* R4 = (const float4*)(Rs + (c << 6) + (jg << 4));
#pragma unroll
        for (int w = 0; w < 4; w++) {
            float4 rv = R4[w];
            r[w * 4 + 0] = fmaf(xv, rv.x, r[w * 4 + 0]);
            r[w * 4 + 1] = fmaf(xv, rv.y, r[w * 4 + 1]);
            r[w * 4 + 2] = fmaf(xv, rv.z, r[w * 4 + 2]);
            r[w * 4 + 3] = fmaf(xv, rv.w, r[w * 4 + 3]);
        }
    }
    int n = (b << 12) + hw0 + tok;
    float4* o4 = (float4*)(g_xrot + (size_t)n * 64 + (jg << 4));
#pragma unroll
    for (int w = 0; w < 4; w++) {
        float4 v; v.x = r[w*4+0]; v.y = r[w*4+1]; v.z = r[w*4+2]; v.w = r[w*4+3];
        o4[w] = v;
    }
    // x2: mul-then-add (unfused), partial per jg, sequential combine
    float s = 0.f;
#pragma unroll
    for (int i = 0; i < 16; i++) s = __fadd_rn(s, __fmul_rn(r[i], r[i]));
    sp[jg][tok] = s;
    __syncthreads();
    if (jg == 0)
        g_x2[n] = __fadd_rn(__fadd_rn(__fadd_rn(sp[0][tok], sp[1][tok]), sp[2][tok]), sp[3][tok]);
}

// ---------------- kernel: e2 per code ----------------------------------------
__global__ void k_e2(const float* __restrict__ E) {
    int k = blockIdx.x * 256 + threadIdx.x;
    if (k < KC) {
        const float* e = E + (size_t)k * 64;
        float s = 0.f;
        for (int d = 0; d < 64; d++) s = __fadd_rn(s, __fmul_rn(e[d], e[d]));
        g_e2[k] = s;
    }
}

// ---------------- kernel: distance GEMM + fused argmin ----------------------
// grid 512 blocks (128 tokens each), 256 threads, loops 8 chunks of 128 codes
// dynamic smem: xs 32K | es 32K (reused as reduce area) | se2 4K | sx2 512B
#define GEMM_SMEM (32768 + 32768 + 4096 + 512)
__global__ void __launch_bounds__(256, 2) k_gemm(const float* __restrict__ E,
                                                 float* __restrict__ out_idx_f) {
    extern __shared__ char sm[];
    float* xs  = (float*)sm;                    // [64][128] k-major
    float* es  = (float*)(sm + 32768);          // [64][128] k-major
    float* se2 = (float*)(sm + 65536);          // [1024]
    float* sx2 = (float*)(sm + 69632);          // [128]
    float* redd = es;                           // overlay after chunk loop
    int*   redj = (int*)(sm + 32768 + 8192);

    int t = threadIdx.x;
    int m0 = blockIdx.x << 7;

    const float4* xr4 = (const float4*)g_xrot + ((size_t)m0 << 4);
#pragma unroll
    for (int q = 0; q < 8; q++) {
        int lin = (q << 8) + t;
        int tok = lin & 127, kq = lin >> 7;     // kq 0..15 (float4 per row)
        float4 v = xr4[(tok << 4) + kq];
        int kb = kq << 2;
        xs[(kb + 0) * 128 + tok] = v.x;
        xs[(kb + 1) * 128 + tok] = v.y;
        xs[(kb + 2) * 128 + tok] = v.z;
        xs[(kb + 3) * 128 + tok] = v.w;
    }
    for (int i = t; i < 1024; i += 256) se2[i] = g_e2[i];
    if (t < 128) sx2[t] = g_x2[m0 + t];

    int rr = t >> 4, cr = t & 15;               // 16x16 thread grid, 8x8 tiles
    float bestd[8]; int bestj[8];
#pragma unroll
    for (int i = 0; i < 8; i++) { bestd[i] = __int_as_float(0x7f800000); bestj[i] = 0; }

    for (int ch = 0; ch < 8; ch++) {
        int c0 = ch << 7;
        __syncthreads();                        // guards xs/se2/sx2 (ch=0) and es reuse
        const float4* e4 = (const float4*)E + ((size_t)c0 << 4);
#pragma unroll
        for (int q = 0; q < 8; q++) {
            int lin = (q << 8) + t;
            int code = lin & 127, kq = lin >> 7;
            float4 v = e4[(code << 4) + kq];
            int kb = kq << 2;
            es[(kb + 0) * 128 + code] = v.x;
            es[(kb + 1) * 128 + code] = v.y;
            es[(kb + 2) * 128 + code] = v.z;
            es[(kb + 3) * 128 + code] = v.w;
        }
        __syncthreads();

        ull acc[4][8];
#pragma unroll
        for (int a = 0; a < 4; a++)
#pragma unroll
            for (int b = 0; b < 8; b++) acc[a][b] = 0ull;

        const float4* XS = (const float4*)xs;
        const float4* ES = (const float4*)es;
#pragma unroll 8
        for (int kk = 0; kk < 64; kk++) {       // sequential k accumulation
            float4 a0 = XS[(kk << 5) + (rr << 1)];
            float4 a1 = XS[(kk << 5) + (rr << 1) + 1];
            float4 b0 = ES[(kk << 5) + (cr << 1)];
            float4 b1 = ES[(kk << 5) + (cr << 1) + 1];
            ull xp0 = pk2(a0.x, a0.y), xp1 = pk2(a0.z, a0.w);
            ull xp2 = pk2(a1.x, a1.y), xp3 = pk2(a1.z, a1.w);
            float ev[8] = {b0.x, b0.y, b0.z, b0.w, b1.x, b1.y, b1.z, b1.w};
#pragma unroll
            for (int cc = 0; cc < 8; cc++) {
                ull ee = pk2(ev[cc], ev[cc]);
                acc[0][cc] = fma2(xp0, ee, acc[0][cc]);
                acc[1][cc] = fma2(xp1, ee, acc[1][cc]);
                acc[2][cc] = fma2(xp2, ee, acc[2][cc]);
                acc[3][cc] = fma2(xp3, ee, acc[3][cc]);
            }
        }
        // dist = fl(fl(x2+e2) - 2*dot); ascending j, strict < => first-min
#pragma unroll
        for (int cc = 0; cc < 8; cc++) {
            int j = c0 + (cr << 3) + cc;
            float e2v = se2[j];
#pragma unroll
            for (int tp = 0; tp < 4; tp++) {
                float d0, d1; upk2(acc[tp][cc], d0, d1);
                int l0 = tp << 1, l1 = l0 + 1;
                float dist0 = __fadd_rn(__fadd_rn(sx2[(rr << 3) + l0], e2v), -2.0f * d0);
                if (dist0 < bestd[l0]) { bestd[l0] = dist0; bestj[l0] = j; }
                float dist1 = __fadd_rn(__fadd_rn(sx2[(rr << 3) + l1], e2v), -2.0f * d1);
                if (dist1 < bestd[l1]) { bestd[l1] = dist1; bestj[l1] = j; }
            }
        }
    }
    __syncthreads();
#pragma unroll
    for (int i = 0; i < 8; i++) {
        redd[cr * 128 + (rr << 3) + i] = bestd[i];
        redj[cr * 128 + (rr << 3) + i] = bestj[i];
    }
    __syncthreads();
    if (t < 128) {  // lexicographic (dist, j) min == global first-index argmin
        float bd = __int_as_float(0x7f800000); int bj = KC;
        for (int c = 0; c < 16; c++) {
            float d = redd[c * 128 + t]; int j = redj[c * 128 + t];
            if (d < bd || (d == bd && j < bj)) { bd = d; bj = j; }
        }
        g_idx[m0 + t] = bj;
        out_idx_f[m0 + t] = (float)bj;
    }
}

// ---------------- kernel: counts + dw (segment sums) ------------------------
// block: 64 threads handle 64 tokens; thread = feature dim d
__global__ void k_stats() {
    __shared__ int sk[64];
    int t = threadIdx.x;
    int n0 = blockIdx.x << 6;
    sk[t] = g_idx[n0 + t];
    __syncthreads();
    atomicAdd(&g_counts[sk[t]], 1);
    for (int tt = 0; tt < 64; tt++) {
        int k = sk[tt];
        double v = (double)g_xrot[(size_t)(n0 + tt) * 64 + t];
        atomicAdd(&g_dw[k * 64 + t], v);
    }
}

// ---------------- kernel: quant_out (STE) + mse ------------------------------
__global__ void k_quant(const float* __restrict__ X, const float* __restrict__ E,
                        float* __restrict__ out) {
    __shared__ double sh[256];
    int t = threadIdx.x;
    int g = blockIdx.x * 256 + t;
    int hw = g & 4095, c = (g >> 12) & 63, b = g >> 18;
    int n = (b << 12) | hw;
    int k = g_idx[n];
    float x = X[g];
    float q = E[(k << 6) + c];
    float df = __fsub_rn(q, x);
    out[g] = __fadd_rn(x, df);          // x + sg(quant - x), fp32 like ref
    sh[t] = (double)df * (double)df;
    __syncthreads();
    for (int s = 128; s > 0; s >>= 1) {
        if (t < s) sh[t] += sh[t + s];
        __syncthreads();
    }
    if (t == 0) atomicAdd(&g_mse, sh[0]);
}

// ---------------- kernel: entropy / loss / new_cs ----------------------------
__global__ void k_final(const float* __restrict__ cs_in, float* __restrict__ out) {
    __shared__ double sh[1024];
    int t = threadIdx.x;
    int c = g_counts[t];
    double p = (double)c / 65536.0;
    sh[t] = -p * log(p + 1e-10);
    __syncthreads();
    for (int s = 512; s > 0; s >>= 1) { if (t < s) sh[t] += sh[t + s]; __syncthreads(); }
    double entropy = sh[0];
    __syncthreads();
    double pre = (double)cs_in[t] * 0.99 + 0.01 * (double)c;
    sh[t] = pre;
    __syncthreads();
    for (int s = 512; s > 0; s >>= 1) { if (t < s) sh[t] += sh[t + s]; __syncthreads(); }
    double n_tot = sh[0];
    double ncs = (pre + 1e-5) / (n_tot + 1024.0 * 1e-5) * n_tot;
    out[OFF_CS + t] = (float)ncs;
    g_newcs[t] = (float)ncs;
    if (t == 0) {
        double mse = g_mse / (double)NELEM;
        out[OFF_LOSS] = (float)(mse * 1.25 + entropy);  // codebook + 0.25*commit + entropy
    }
}

// ---------------- kernel: new_ema_w + new_embedding --------------------------
__global__ void k_ema(const float* __restrict__ ema_w, float* __restrict__ out) {
    int i = blockIdx.x * 256 + threadIdx.x;   // 65536
    float w = ema_w[i] * 0.99f + 0.01f * (float)g_dw[i];
    out[OFF_EMAW + i] = w;
    out[OFF_EMB + i] = w / g_newcs[i >> 6];
}

// ---------------- launcher ---------------------------------------------------
extern "C" void kernel_launch(void* const* d_in, const int* in_sizes, int n_in,
                              void* d_out, int out_size) {
    const float* X   = (const float*)d_in[0];  // [16,64,64,64]
    const float* E   = (const float*)d_in[1];  // [1024,64]
    const float* R   = (const float*)d_in[2];  // [64,64]
    const float* CS  = (const float*)d_in[3];  // [1024]
    const float* EW  = (const float*)d_in[4];  // [1024,64]
    float* out = (float*)d_out;

    static bool attr_set = false;
    if (!attr_set) {
        cudaFuncSetAttribute(k_gemm, cudaFuncAttributeMaxDynamicSharedMemorySize, GEMM_SMEM);
        attr_set = true;
    }

    k_zero<<<256, 256>>>();
    k_rotate<<<1024, 256>>>(X, R);
    k_e2<<<4, 256>>>(E);
    k_gemm<<<512, 256, GEMM_SMEM>>>(E, out + OFF_IDX);
    k_stats<<<1024, 64>>>();
    k_quant<<<16384, 256>>>(X, E, out);
    k_final<<<1, 1024>>>(CS, out);
    k_ema<<<256, 256>>>(EW, out);
}

// round 3
// speedup vs baseline: 1.1100x; 1.1100x over previous
#include <cuda_runtime.h>
#include <math.h>

#define N_TOK 65536
#define DD 64
#define KC 1024
#define NELEM 4194304
#define OFF_LOSS 4194304
#define OFF_IDX  4194305
#define OFF_EMB  4259841
#define OFF_CS   4325377
#define OFF_EMAW 4326401

// ---------------- scratch (device globals; no allocations allowed) ----------
__device__ float  g_xrot[N_TOK * DD];   // rotated tokens, row-major [n][d]
__device__ float  g_x2[N_TOK];          // ||x_rot||^2 per token (fp32, ref-like)
__device__ float  g_e2[KC];             // ||e||^2 per code
__device__ int    g_idx[N_TOK];
__device__ int    g_counts[KC];
__device__ float  g_dwf[KC * DD];       // segment-sum of x_rot (fp32 atomics)
__device__ double g_mse;                // sum of (quant-x)^2
__device__ float  g_newcs[KC];

typedef unsigned long long ull;

__device__ __forceinline__ ull pk2(float lo, float hi) {
    ull r; asm("mov.b64 %0, {%1, %2};" : "=l"(r) : "f"(lo), "f"(hi)); return r;
}
__device__ __forceinline__ void upk2(ull v, float &lo, float &hi) {
    asm("mov.b64 {%0, %1}, %2;" : "=f"(lo), "=f"(hi) : "l"(v));
}
__device__ __forceinline__ ull fma2(ull a, ull b, ull c) {
    ull d; asm("fma.rn.f32x2 %0, %1, %2, %3;" : "=l"(d) : "l"(a), "l"(b), "l"(c)); return d;
}

// ---------------- kernel: zero scratch + e2 (fused) --------------------------
__global__ void k_init(const float* __restrict__ E) {
    int b = blockIdx.x, t = threadIdx.x;
    if (b < 256) {
        int i = b * 256 + t;
        g_dwf[i] = 0.f;
        if (i < KC) g_counts[i] = 0;
        if (i == 0) g_mse = 0.0;
    } else {
        int k = (b - 256) * 256 + t;     // 0..1023
        const float4* e = (const float4*)(E + ((size_t)k << 6));
        float s = 0.f;
#pragma unroll
        for (int q = 0; q < 16; q++) {   // sequential d order (matches R1-验证 order)
            float4 v = e[q];
            s = __fadd_rn(s, __fmul_rn(v.x, v.x));
            s = __fadd_rn(s, __fmul_rn(v.y, v.y));
            s = __fadd_rn(s, __fmul_rn(v.z, v.z));
            s = __fadd_rn(s, __fmul_rn(v.w, v.w));
        }
        g_e2[k] = s;
    }
}

// ---------------- kernel: rotation x_rot = x_flat @ R, plus x2 --------------
// UNCHANGED numerics from R1 (bit-exact idx depends on it)
__global__ void k_rotate(const float* __restrict__ X, const float* __restrict__ R) {
    __shared__ float Rs[64 * 64];
    __shared__ float xs[64 * 64];
    __shared__ float sp[4][64];
    int t = threadIdx.x;
    int b = blockIdx.x >> 6;
    int hw0 = (blockIdx.x & 63) << 6;

    for (int i = t; i < 4096; i += 256) Rs[i] = R[i];
    for (int i = t; i < 4096; i += 256) {
        int c = i >> 6, w = i & 63;
        xs[i] = X[(((b << 6) + c) << 12) + hw0 + w];
    }
    __syncthreads();

    int tok = t & 63, jg = t >> 6;
    float r[16];
#pragma unroll
    for (int i = 0; i < 16; i++) r[i] = 0.f;

#pragma unroll 8
    for (int c = 0; c < 64; c++) {
        float xv = xs[(c << 6) + tok];
        const float4* R4 = (const float4*)(Rs + (c << 6) + (jg << 4));
#pragma unroll
        for (int w = 0; w < 4; w++) {
            float4 rv = R4[w];
            r[w * 4 + 0] = fmaf(xv, rv.x, r[w * 4 + 0]);
            r[w * 4 + 1] = fmaf(xv, rv.y, r[w * 4 + 1]);
            r[w * 4 + 2] = fmaf(xv, rv.z, r[w * 4 + 2]);
            r[w * 4 + 3] = fmaf(xv, rv.w, r[w * 4 + 3]);
        }
    }
    int n = (b << 12) + hw0 + tok;
    float4* o4 = (float4*)(g_xrot + (size_t)n * 64 + (jg << 4));
#pragma unroll
    for (int w = 0; w < 4; w++) {
        float4 v; v.x = r[w*4+0]; v.y = r[w*4+1]; v.z = r[w*4+2]; v.w = r[w*4+3];
        o4[w] = v;
    }
    float s = 0.f;
#pragma unroll
    for (int i = 0; i < 16; i++) s = __fadd_rn(s, __fmul_rn(r[i], r[i]));
    sp[jg][tok] = s;
    __syncthreads();
    if (jg == 0)
        g_x2[n] = __fadd_rn(__fadd_rn(__fadd_rn(sp[0][tok], sp[1][tok]), sp[2][tok]), sp[3][tok]);
}

// ---------------- kernel: distance GEMM + fused argmin ----------------------
// 512 blocks x 256 threads; tile 128 tok x 128 codes; 8 chunks of 128 codes.
// Double-buffered es smem (one sync/chunk) + register staging of next E chunk.
// Warp layout: rr spans 4, cr spans 8 -> all LDS fragments <=128B unique/warp.
#define GEMM_SMEM (32768 * 3 + 4096 + 512)
__global__ void __launch_bounds__(256, 2) k_gemm(const float* __restrict__ E,
                                                 float* __restrict__ out_idx_f) {
    extern __shared__ char sm[];
    float* xs  = (float*)sm;                    // [64][128] k-major
    float* esb[2] = { (float*)(sm + 32768), (float*)(sm + 65536) };
    float* se2 = (float*)(sm + 98304);          // [1024]
    float* sx2 = (float*)(sm + 102400);         // [128]
    float* redd = esb[0];
    int*   redj = (int*)(esb[0] + 2048);

    int t = threadIdx.x;
    int w = t >> 5, lane = t & 31;
    int rr = ((w >> 1) << 2) | (lane >> 3);     // 0..15, spans 4 per warp
    int cr = ((w & 1) << 3) | (lane & 7);       // 0..15, spans 8 per warp
    int m0 = blockIdx.x << 7;

    const float4* xr4 = (const float4*)g_xrot + ((size_t)m0 << 4);
#pragma unroll
    for (int q = 0; q < 8; q++) {
        int lin = (q << 8) + t;
        int tok = lin & 127, kq = lin >> 7, kb = kq << 2;
        float4 v = xr4[(tok << 4) + kq];
        xs[(kb + 0) * 128 + tok] = v.x;
        xs[(kb + 1) * 128 + tok] = v.y;
        xs[(kb + 2) * 128 + tok] = v.z;
        xs[(kb + 3) * 128 + tok] = v.w;
    }
    for (int i = t; i < 1024; i += 256) se2[i] = g_e2[i];
    if (t < 128) sx2[t] = g_x2[m0 + t];

    // stage chunk 0 of E in registers
    const float4* e4 = (const float4*)E;
    float4 stg[8];
#pragma unroll
    for (int q = 0; q < 8; q++) {
        int lin = (q << 8) + t;
        stg[q] = e4[((lin & 127) << 4) + (lin >> 7)];
    }

    float bestd[8]; int bestj[8];
#pragma unroll
    for (int i = 0; i < 8; i++) { bestd[i] = __int_as_float(0x7f800000); bestj[i] = 0; }

    for (int ch = 0; ch < 8; ch++) {
        float* es = esb[ch & 1];
        // commit staged chunk to smem (transpose to k-major)
#pragma unroll
        for (int q = 0; q < 8; q++) {
            int lin = (q << 8) + t;
            int code = lin & 127, kb = (lin >> 7) << 2;
            es[(kb + 0) * 128 + code] = stg[q].x;
            es[(kb + 1) * 128 + code] = stg[q].y;
            es[(kb + 2) * 128 + code] = stg[q].z;
            es[(kb + 3) * 128 + code] = stg[q].w;
        }
        __syncthreads();                        // single sync per chunk
        // prefetch next chunk into staging regs (overlaps with compute)
        if (ch < 7) {
            const float4* en = e4 + ((size_t)(ch + 1) << 11);
#pragma unroll
            for (int q = 0; q < 8; q++) {
                int lin = (q << 8) + t;
                stg[q] = en[((lin & 127) << 4) + (lin >> 7)];
            }
        }

        ull acc[4][8];
#pragma unroll
        for (int a = 0; a < 4; a++)
#pragma unroll
            for (int b = 0; b < 8; b++) acc[a][b] = 0ull;

        const float4* XS = (const float4*)xs;
        const float4* ES = (const float4*)es;
#pragma unroll 8
        for (int kk = 0; kk < 64; kk++) {       // sequential k accumulation
            float4 a0 = XS[(kk << 5) + (rr << 1)];
            float4 a1 = XS[(kk << 5) + (rr << 1) + 1];
            float4 b0 = ES[(kk << 5) + (cr << 1)];
            float4 b1 = ES[(kk << 5) + (cr << 1) + 1];
            ull xp0 = pk2(a0.x, a0.y), xp1 = pk2(a0.z, a0.w);
            ull xp2 = pk2(a1.x, a1.y), xp3 = pk2(a1.z, a1.w);
            float ev[8] = {b0.x, b0.y, b0.z, b0.w, b1.x, b1.y, b1.z, b1.w};
#pragma unroll
            for (int cc = 0; cc < 8; cc++) {
                ull ee = pk2(ev[cc], ev[cc]);
                acc[0][cc] = fma2(xp0, ee, acc[0][cc]);
                acc[1][cc] = fma2(xp1, ee, acc[1][cc]);
                acc[2][cc] = fma2(xp2, ee, acc[2][cc]);
                acc[3][cc] = fma2(xp3, ee, acc[3][cc]);
            }
        }
        // dist = fl(fl(x2+e2) - 2*dot); ascending j, strict < => first-min
        int c0 = ch << 7;
#pragma unroll
        for (int cc = 0; cc < 8; cc++) {
            int j = c0 + (cr << 3) + cc;
            float e2v = se2[j];
#pragma unroll
            for (int tp = 0; tp < 4; tp++) {
                float d0, d1; upk2(acc[tp][cc], d0, d1);
                int l0 = tp << 1, l1 = l0 + 1;
                float dist0 = __fadd_rn(__fadd_rn(sx2[(rr << 3) + l0], e2v), -2.0f * d0);
                if (dist0 < bestd[l0]) { bestd[l0] = dist0; bestj[l0] = j; }
                float dist1 = __fadd_rn(__fadd_rn(sx2[(rr << 3) + l1], e2v), -2.0f * d1);
                if (dist1 < bestd[l1]) { bestd[l1] = dist1; bestj[l1] = j; }
            }
        }
        // no trailing sync: next iter writes the other buffer; its top sync
        // only follows after every thread finished this compute.
    }
    __syncthreads();
#pragma unroll
    for (int i = 0; i < 8; i++) {
        redd[cr * 128 + (rr << 3) + i] = bestd[i];
        redj[cr * 128 + (rr << 3) + i] = bestj[i];
    }
    __syncthreads();
    if (t < 128) {  // lexicographic (dist, j) min == global first-index argmin
        float bd = __int_as_float(0x7f800000); int bj = KC;
        for (int c = 0; c < 16; c++) {
            float d = redd[c * 128 + t]; int j = redj[c * 128 + t];
            if (d < bd || (d == bd && j < bj)) { bd = d; bj = j; }
        }
        g_idx[m0 + t] = bj;
        out_idx_f[m0 + t] = (float)bj;
    }
}

// ---------------- kernel: counts + dw (fully parallel fp32 REDs) ------------
__global__ void k_stats() {
    int t = threadIdx.x;                 // 256
    int n = (blockIdx.x << 2) + (t >> 6);
    int d = t & 63;
    int k = g_idx[n];
    atomicAdd(&g_dwf[(k << 6) + d], g_xrot[((size_t)n << 6) + d]);
    if (d == 0) atomicAdd(&g_counts[k], 1);
}

// ---------------- kernel: quant_out (STE) + mse, float4 IO -------------------
__global__ void k_quant(const float* __restrict__ X, const float* __restrict__ E,
                        float* __restrict__ out) {
    int pane = blockIdx.x;               // b*64 + c, one 4096-elem pane
    int c = pane & 63, b = pane >> 6;
    int t = threadIdx.x;
    size_t base = (size_t)pane << 12;
    const float4* X4 = (const float4*)(X + base);
    float4* O4 = (float4*)(out + base);
    const int4* I4 = (const int4*)(g_idx + ((size_t)b << 12));
    double acc = 0.0;
#pragma unroll
    for (int r = 0; r < 4; r++) {
        int i = (r << 8) + t;
        float4 x = X4[i];
        int4 kv = I4[i];
        float q0 = E[(kv.x << 6) + c], q1 = E[(kv.y << 6) + c];
        float q2 = E[(kv.z << 6) + c], q3 = E[(kv.w << 6) + c];
        float d0 = __fsub_rn(q0, x.x), d1 = __fsub_rn(q1, x.y);
        float d2 = __fsub_rn(q2, x.z), d3 = __fsub_rn(q3, x.w);
        float4 o;
        o.x = __fadd_rn(x.x, d0); o.y = __fadd_rn(x.y, d1);
        o.z = __fadd_rn(x.z, d2); o.w = __fadd_rn(x.w, d3);
        O4[i] = o;
        acc += (double)d0 * d0 + (double)d1 * d1 + (double)d2 * d2 + (double)d3 * d3;
    }
#pragma unroll
    for (int o = 16; o; o >>= 1) acc += __shfl_down_sync(0xffffffffu, acc, o);
    __shared__ double sw[8];
    if ((t & 31) == 0) sw[t >> 5] = acc;
    __syncthreads();
    if (t == 0) {
        double s = 0.0;
        for (int i = 0; i < 8; i++) s += sw[i];
        atomicAdd(&g_mse, s);
    }
}

// ---------------- kernel: entropy / loss / new_cs ----------------------------
__global__ void k_final(const float* __restrict__ cs_in, float* __restrict__ out) {
    __shared__ double sh[1024];
    int t = threadIdx.x;
    int c = g_counts[t];
    double p = (double)c / 65536.0;
    sh[t] = -p * log(p + 1e-10);
    __syncthreads();
    for (int s = 512; s > 0; s >>= 1) { if (t < s) sh[t] += sh[t + s]; __syncthreads(); }
    double entropy = sh[0];
    __syncthreads();
    double pre = (double)cs_in[t] * 0.99 + 0.01 * (double)c;
    sh[t] = pre;
    __syncthreads();
    for (int s = 512; s > 0; s >>= 1) { if (t < s) sh[t] += sh[t + s]; __syncthreads(); }
    double n_tot = sh[0];
    double ncs = (pre + 1e-5) / (n_tot + 1024.0 * 1e-5) * n_tot;
    out[OFF_CS + t] = (float)ncs;
    g_newcs[t] = (float)ncs;
    if (t == 0) {
        double mse = g_mse / (double)NELEM;
        out[OFF_LOSS] = (float)(mse * 1.25 + entropy);
    }
}

// ---------------- kernel: new_ema_w + new_embedding --------------------------
__global__ void k_ema(const float* __restrict__ ema_w, float* __restrict__ out) {
    int i = blockIdx.x * 256 + threadIdx.x;   // 65536
    float w = ema_w[i] * 0.99f + 0.01f * g_dwf[i];
    out[OFF_EMAW + i] = w;
    out[OFF_EMB + i] = w / g_newcs[i >> 6];
}

// ---------------- launcher ---------------------------------------------------
extern "C" void kernel_launch(void* const* d_in, const int* in_sizes, int n_in,
                              void* d_out, int out_size) {
    const float* X   = (const float*)d_in[0];
    const float* E   = (const float*)d_in[1];
    const float* R   = (const float*)d_in[2];
    const float* CS  = (const float*)d_in[3];
    const float* EW  = (const float*)d_in[4];
    float* out = (float*)d_out;

    static bool attr_set = false;
    if (!attr_set) {
        cudaFuncSetAttribute(k_gemm, cudaFuncAttributeMaxDynamicSharedMemorySize, GEMM_SMEM);
        attr_set = true;
    }

    k_init<<<260, 256>>>(E);
    k_rotate<<<1024, 256>>>(X, R);
    k_gemm<<<512, 256, GEMM_SMEM>>>(E, out + OFF_IDX);
    k_stats<<<16384, 256>>>();
    k_quant<<<1024, 256>>>(X, E, out);
    k_final<<<1, 1024>>>(CS, out);
    k_ema<<<256, 256>>>(EW, out);
}